// round 2
// baseline (speedup 1.0000x reference)
#include <cuda_runtime.h>
#include <cstdint>

// ---------------------------------------------------------------------------
// GCNconv: out = segment_sum(edge_val * (x @ W)[edge_dst], edge_src) + bias
//   x        [N, 256] f32
//   weight   [256, 256] f32
//   bias     [256] f32
//   edge_val [E] f32
//   edge_src [E] i32   (output row)
//   edge_dst [E] i32   (gather row of h)
// out [N, 256] f32
// ---------------------------------------------------------------------------

#define IN_DIM  256
#define OUT_DIM 256
#define MAX_NODES 100000

// Scratch for h = x @ W  (102.4 MB). Device-global per allocation rules.
__device__ float g_h[(size_t)MAX_NODES * OUT_DIM];

// ---------------------------------------------------------------------------
// Kernel 1: out[i, :] = bias[:]
// ---------------------------------------------------------------------------
__global__ void init_bias_kernel(float* __restrict__ out,
                                 const float* __restrict__ bias,
                                 int total_f4) {
    int idx = blockIdx.x * blockDim.x + threadIdx.x;
    if (idx >= total_f4) return;
    const float4* b4 = reinterpret_cast<const float4*>(bias);
    float4 v = b4[idx & (OUT_DIM / 4 - 1)];
    reinterpret_cast<float4*>(out)[idx] = v;
}

// ---------------------------------------------------------------------------
// Kernel 2: tiled fp32 GEMM  h = x @ W
//   BM=64, BN=64, BK=32, 256 threads, 4x4 micro-tile per thread.
// ---------------------------------------------------------------------------
#define BM 64
#define BN 64
#define BK 32

__global__ __launch_bounds__(256) void gemm_kernel(
    const float* __restrict__ A,   // [M, 256]
    const float* __restrict__ B,   // [256, 256]
    int M) {
    __shared__ float As[BK][BM];   // A tile, transposed (k-major)
    __shared__ float Bs[BK][BN];

    const int tid = threadIdx.x;
    const int tx = tid & 15;        // 0..15  -> n
    const int ty = tid >> 4;        // 0..15  -> m
    const int m0 = blockIdx.y * BM;
    const int n0 = blockIdx.x * BN;

    float acc[4][4] = {};

    for (int k0 = 0; k0 < IN_DIM; k0 += BK) {
        // --- load A tile: 64 rows x 32 cols = 512 float4, 2 per thread ---
#pragma unroll
        for (int i = 0; i < 2; i++) {
            int idx = tid + i * 256;        // 0..511
            int row = idx >> 3;             // 0..63
            int kc  = (idx & 7) * 4;        // 0..28
            float4 v = make_float4(0.f, 0.f, 0.f, 0.f);
            int gm = m0 + row;
            if (gm < M)
                v = *reinterpret_cast<const float4*>(A + (size_t)gm * IN_DIM + k0 + kc);
            As[kc + 0][row] = v.x;
            As[kc + 1][row] = v.y;
            As[kc + 2][row] = v.z;
            As[kc + 3][row] = v.w;
        }
        // --- load B tile: 32 rows x 64 cols = 512 float4, 2 per thread ---
#pragma unroll
        for (int i = 0; i < 2; i++) {
            int idx = tid + i * 256;
            int row = idx >> 4;             // 0..31
            int nc  = (idx & 15) * 4;       // 0..60
            float4 v = *reinterpret_cast<const float4*>(
                B + (size_t)(k0 + row) * OUT_DIM + n0 + nc);
            *reinterpret_cast<float4*>(&Bs[row][nc]) = v;
        }
        __syncthreads();

#pragma unroll
        for (int kk = 0; kk < BK; kk++) {
            float4 a4 = *reinterpret_cast<const float4*>(&As[kk][ty * 4]);
            float4 b4 = *reinterpret_cast<const float4*>(&Bs[kk][tx * 4]);
            float av[4] = {a4.x, a4.y, a4.z, a4.w};
            float bv[4] = {b4.x, b4.y, b4.z, b4.w};
#pragma unroll
            for (int i = 0; i < 4; i++)
#pragma unroll
                for (int j = 0; j < 4; j++)
                    acc[i][j] += av[i] * bv[j];
        }
        __syncthreads();
    }

#pragma unroll
    for (int i = 0; i < 4; i++) {
        int row = m0 + ty * 4 + i;
        if (row < M) {
            float4 v = make_float4(acc[i][0], acc[i][1], acc[i][2], acc[i][3]);
            *reinterpret_cast<float4*>(&g_h[(size_t)row * OUT_DIM + n0 + tx * 4]) = v;
        }
    }
}

// ---------------------------------------------------------------------------
// Kernel 3: edge scatter. One warp per edge.
//   Each lane handles 2 float4 (256 floats / 32 lanes = 8 floats).
//   Accumulate into out[src] via red.global.add.v4.f32 (no-return reduction).
// ---------------------------------------------------------------------------
__global__ __launch_bounds__(256) void scatter_kernel(
    const float* __restrict__ ev,
    const int* __restrict__ esrc,
    const int* __restrict__ edst,
    float* __restrict__ out,
    int E) {
    int gwid = (blockIdx.x * blockDim.x + threadIdx.x) >> 5;
    if (gwid >= E) return;
    int lane = threadIdx.x & 31;

    int s = __ldg(esrc + gwid);
    int d = __ldg(edst + gwid);
    float v = __ldg(ev + gwid);

    const float4* hp = reinterpret_cast<const float4*>(g_h + (size_t)d * OUT_DIM);
    float4* op = reinterpret_cast<float4*>(out + (size_t)s * OUT_DIM);

#pragma unroll
    for (int i = 0; i < 2; i++) {
        float4 m = hp[lane + i * 32];
        m.x *= v; m.y *= v; m.z *= v; m.w *= v;
        asm volatile(
            "red.global.add.v4.f32 [%0], {%1, %2, %3, %4};"
            :: "l"(op + lane + i * 32), "f"(m.x), "f"(m.y), "f"(m.z), "f"(m.w)
            : "memory");
    }
}

// ---------------------------------------------------------------------------
// Launch
// ---------------------------------------------------------------------------
extern "C" void kernel_launch(void* const* d_in, const int* in_sizes, int n_in,
                              void* d_out, int out_size) {
    const float* x    = (const float*)d_in[0];
    const float* w    = (const float*)d_in[1];
    const float* bias = (const float*)d_in[2];
    const float* ev   = (const float*)d_in[3];
    const int*   esrc = (const int*)d_in[4];
    const int*   edst = (const int*)d_in[5];
    float* out = (float*)d_out;

    const int M = in_sizes[0] / IN_DIM;    // 100000
    const int E = in_sizes[3];             // 3200000

    // 1) out = bias (broadcast)
    int total_f4 = M * (OUT_DIM / 4);
    init_bias_kernel<<<(total_f4 + 255) / 256, 256>>>(out, bias, total_f4);

    // 2) h = x @ W
    dim3 gg(OUT_DIM / BN, (M + BM - 1) / BM);
    gemm_kernel<<<gg, 256>>>(x, w, M);

    // 3) out[src] += ev * h[dst]   (one warp per edge)
    long long threads = (long long)E * 32;
    int blocks = (int)((threads + 255) / 256);
    scatter_kernel<<<blocks, 256>>>(ev, esrc, edst, out, E);
}

// round 4
// speedup vs baseline: 1.7991x; 1.7991x over previous
#include <cuda_runtime.h>
#include <cstdint>

// ---------------------------------------------------------------------------
// GCNconv: out = segment_sum(edge_val * (x @ W)[edge_dst], edge_src) + bias
//   x[N,256] f32, weight[256,256] f32, bias[256] f32,
//   edge_val[E] f32, edge_src[E] i32 (out row), edge_dst[E] i32 (gather row)
// out [N, 256] f32
//
// Pipeline (single stream, graph-capturable):
//   1. zero counters
//   2. h = x @ W                       (tiled SIMT GEMM)
//   3. degree histogram over edge_src
//   4. exclusive scan -> CSR offsets   (3-kernel scan)
//   5. bucket scatter (dst,val) into segment-sorted arrays
//   6. gather-side aggregate: out[n] = bias + sum_seg val * h[dst]  (no atomics on out)
// ---------------------------------------------------------------------------

#define IN_DIM  256
#define OUT_DIM 256
#define MAX_NODES 100000
#define MAX_EDGES 3200000
#define SCAN_B 512
#define MAX_SCAN_BLOCKS 256   // ceil(100000/512) = 196 <= 256

// Scratch (device globals per allocation rules). ~130 MB total.
__device__ float g_h[(size_t)MAX_NODES * OUT_DIM];
__device__ int   g_deg[MAX_NODES];
__device__ int   g_cnt[MAX_NODES];
__device__ int   g_part[MAX_NODES];
__device__ int   g_sums[MAX_SCAN_BLOCKS];
__device__ int   g_off[MAX_NODES + 1];
__device__ int   g_sdst[MAX_EDGES];
__device__ float g_sval[MAX_EDGES];

// ---------------------------------------------------------------------------
// 1) zero deg + cnt
// ---------------------------------------------------------------------------
__global__ void zero_kernel(int M) {
    int i = blockIdx.x * blockDim.x + threadIdx.x;
    if (i < M) { g_deg[i] = 0; g_cnt[i] = 0; }
}

// ---------------------------------------------------------------------------
// 2) tiled fp32 GEMM  h = x @ W   (BM=64, BN=64, BK=32, 256 thr, 4x4 microtile)
// ---------------------------------------------------------------------------
#define BM 64
#define BN 64
#define BK 32

__global__ __launch_bounds__(256) void gemm_kernel(
    const float* __restrict__ A, const float* __restrict__ B, int M) {
    __shared__ float As[BK][BM];
    __shared__ float Bs[BK][BN];

    const int tid = threadIdx.x;
    const int tx = tid & 15;
    const int ty = tid >> 4;
    const int m0 = blockIdx.y * BM;
    const int n0 = blockIdx.x * BN;

    float acc[4][4] = {};

    for (int k0 = 0; k0 < IN_DIM; k0 += BK) {
#pragma unroll
        for (int i = 0; i < 2; i++) {
            int idx = tid + i * 256;
            int row = idx >> 3;
            int kc  = (idx & 7) * 4;
            float4 v = make_float4(0.f, 0.f, 0.f, 0.f);
            int gm = m0 + row;
            if (gm < M)
                v = *reinterpret_cast<const float4*>(A + (size_t)gm * IN_DIM + k0 + kc);
            As[kc + 0][row] = v.x;
            As[kc + 1][row] = v.y;
            As[kc + 2][row] = v.z;
            As[kc + 3][row] = v.w;
        }
#pragma unroll
        for (int i = 0; i < 2; i++) {
            int idx = tid + i * 256;
            int row = idx >> 4;
            int nc  = (idx & 15) * 4;
            float4 v = *reinterpret_cast<const float4*>(
                B + (size_t)(k0 + row) * OUT_DIM + n0 + nc);
            *reinterpret_cast<float4*>(&Bs[row][nc]) = v;
        }
        __syncthreads();

#pragma unroll
        for (int kk = 0; kk < BK; kk++) {
            float4 a4 = *reinterpret_cast<const float4*>(&As[kk][ty * 4]);
            float4 b4 = *reinterpret_cast<const float4*>(&Bs[kk][tx * 4]);
            float av[4] = {a4.x, a4.y, a4.z, a4.w};
            float bv[4] = {b4.x, b4.y, b4.z, b4.w};
#pragma unroll
            for (int i = 0; i < 4; i++)
#pragma unroll
                for (int j = 0; j < 4; j++)
                    acc[i][j] += av[i] * bv[j];
        }
        __syncthreads();
    }

#pragma unroll
    for (int i = 0; i < 4; i++) {
        int row = m0 + ty * 4 + i;
        if (row < M) {
            float4 v = make_float4(acc[i][0], acc[i][1], acc[i][2], acc[i][3]);
            *reinterpret_cast<float4*>(&g_h[(size_t)row * OUT_DIM + n0 + tx * 4]) = v;
        }
    }
}

// ---------------------------------------------------------------------------
// 3) degree histogram
// ---------------------------------------------------------------------------
__global__ void hist_kernel(const int* __restrict__ esrc, int E) {
    int e = blockIdx.x * blockDim.x + threadIdx.x;
    if (e < E) atomicAdd(&g_deg[__ldg(esrc + e)], 1);
}

// ---------------------------------------------------------------------------
// 4) exclusive scan (3 kernels)
// ---------------------------------------------------------------------------
__global__ __launch_bounds__(SCAN_B) void scan_part_kernel(int M) {
    __shared__ int sh[SCAN_B];
    int gid = blockIdx.x * SCAN_B + threadIdx.x;
    int v = (gid < M) ? g_deg[gid] : 0;
    sh[threadIdx.x] = v;
    __syncthreads();
#pragma unroll
    for (int off = 1; off < SCAN_B; off <<= 1) {
        int t = (threadIdx.x >= off) ? sh[threadIdx.x - off] : 0;
        __syncthreads();
        sh[threadIdx.x] += t;
        __syncthreads();
    }
    if (gid < M) g_part[gid] = sh[threadIdx.x] - v;   // exclusive
    if (threadIdx.x == SCAN_B - 1) g_sums[blockIdx.x] = sh[SCAN_B - 1];
}

__global__ __launch_bounds__(MAX_SCAN_BLOCKS) void scan_tops_kernel(int nb) {
    __shared__ int sh[MAX_SCAN_BLOCKS];
    int v = (threadIdx.x < nb) ? g_sums[threadIdx.x] : 0;
    sh[threadIdx.x] = v;
    __syncthreads();
#pragma unroll
    for (int off = 1; off < MAX_SCAN_BLOCKS; off <<= 1) {
        int t = (threadIdx.x >= off) ? sh[threadIdx.x - off] : 0;
        __syncthreads();
        sh[threadIdx.x] += t;
        __syncthreads();
    }
    if (threadIdx.x < nb) g_sums[threadIdx.x] = sh[threadIdx.x] - v;  // exclusive
}

__global__ void scan_add_kernel(int M, int E) {
    int gid = blockIdx.x * blockDim.x + threadIdx.x;
    if (gid < M) g_off[gid] = g_part[gid] + g_sums[gid / SCAN_B];
    if (gid == 0) g_off[M] = E;
}

// ---------------------------------------------------------------------------
// 5) bucket scatter (dst, val) into segment-sorted arrays
// ---------------------------------------------------------------------------
__global__ void scatter_build_kernel(const int* __restrict__ esrc,
                                     const int* __restrict__ edst,
                                     const float* __restrict__ ev, int E) {
    int e = blockIdx.x * blockDim.x + threadIdx.x;
    if (e >= E) return;
    int s = __ldg(esrc + e);
    int p = g_off[s] + atomicAdd(&g_cnt[s], 1);
    g_sdst[p] = __ldg(edst + e);
    g_sval[p] = __ldg(ev + e);
}

// ---------------------------------------------------------------------------
// 6) gather-side aggregate. 64 threads per node, 4 nodes per 256-thread block.
//    Each thread owns one float4 column slice; acc starts at bias; single write.
// ---------------------------------------------------------------------------
__global__ __launch_bounds__(256) void aggregate_kernel(
    const float* __restrict__ bias, float* __restrict__ out, int M) {
    int node = blockIdx.x * 4 + (threadIdx.x >> 6);
    if (node >= M) return;
    int t = threadIdx.x & 63;    // column group: floats [t*4, t*4+4)

    float4 acc = reinterpret_cast<const float4*>(bias)[t];

    int i   = g_off[node];
    int end = g_off[node + 1];

    // 2-edge unroll for MLP
    for (; i + 1 < end; i += 2) {
        int   d0 = __ldg(g_sdst + i);
        int   d1 = __ldg(g_sdst + i + 1);
        float v0 = __ldg(g_sval + i);
        float v1 = __ldg(g_sval + i + 1);
        float4 h0 = *reinterpret_cast<const float4*>(g_h + (size_t)d0 * OUT_DIM + t * 4);
        float4 h1 = *reinterpret_cast<const float4*>(g_h + (size_t)d1 * OUT_DIM + t * 4);
        acc.x += v0 * h0.x; acc.y += v0 * h0.y; acc.z += v0 * h0.z; acc.w += v0 * h0.w;
        acc.x += v1 * h1.x; acc.y += v1 * h1.y; acc.z += v1 * h1.z; acc.w += v1 * h1.w;
    }
    if (i < end) {
        int   d0 = __ldg(g_sdst + i);
        float v0 = __ldg(g_sval + i);
        float4 h0 = *reinterpret_cast<const float4*>(g_h + (size_t)d0 * OUT_DIM + t * 4);
        acc.x += v0 * h0.x; acc.y += v0 * h0.y; acc.z += v0 * h0.z; acc.w += v0 * h0.w;
    }

    *reinterpret_cast<float4*>(out + (size_t)node * OUT_DIM + t * 4) = acc;
}

// ---------------------------------------------------------------------------
// Launch
// ---------------------------------------------------------------------------
extern "C" void kernel_launch(void* const* d_in, const int* in_sizes, int n_in,
                              void* d_out, int out_size) {
    const float* x    = (const float*)d_in[0];
    const float* w    = (const float*)d_in[1];
    const float* bias = (const float*)d_in[2];
    const float* ev   = (const float*)d_in[3];
    const int*   esrc = (const int*)d_in[4];
    const int*   edst = (const int*)d_in[5];
    float* out = (float*)d_out;

    const int M = in_sizes[0] / IN_DIM;   // 100000
    const int E = in_sizes[3];            // 3200000

    // 1) zero degree/cursor counters
    zero_kernel<<<(M + 255) / 256, 256>>>(M);

    // 2) h = x @ W
    dim3 gg(OUT_DIM / BN, (M + BM - 1) / BM);
    gemm_kernel<<<gg, 256>>>(x, w, M);

    // 3) degree histogram
    hist_kernel<<<(E + 255) / 256, 256>>>(esrc, E);

    // 4) exclusive scan -> CSR offsets
    int nb = (M + SCAN_B - 1) / SCAN_B;   // 196
    scan_part_kernel<<<nb, SCAN_B>>>(M);
    scan_tops_kernel<<<1, MAX_SCAN_BLOCKS>>>(nb);
    scan_add_kernel<<<(M + 255) / 256, 256>>>(M, E);

    // 5) bucket scatter into segment-sorted (dst, val)
    scatter_build_kernel<<<(E + 255) / 256, 256>>>(esrc, edst, ev, E);

    // 6) aggregate: out[n] = bias + sum val * h[dst]
    aggregate_kernel<<<(M + 3) / 4, 256>>>(bias, out, M);
}